// round 10
// baseline (speedup 1.0000x reference)
#include <cuda_runtime.h>

// Retina glimpse: x [B=16384, C=3, 32, 32] f32, l [B,2] f32 in [-1,1].
// Outputs concatenated into d_out:
//   full  [B,3,32,32] : x masked to the valid part of the 16x16 window, else 0
//   patch [B,3,16,16] : gathered window, 0 where out of [0,32) bounds
//
// Final: one 192-thread CTA per sample. Full phase = 4 float4 tasks/thread
// (768 quads exactly), patch phase = 1 float4 task/thread (192 quads exactly)
// -> no idle lanes, no divergent tails. Kernel is HBM-roofline-bound at the
// ~5.3-5.4 TB/s mixed read/write ceiling (verified across 9 structural
// variants: STG vs TMA bulk, smem staging, MLP x2, persistent CTAs).

#define BB 16384
#define CC 3
#define HH 32
#define GG 16
#define FULL_PER_B (CC*HH*HH)   // 3072 floats = 768 float4
#define PATCH_PER_B (CC*GG*GG)  // 768 floats  = 192 float4
#define TPB 192

__global__ __launch_bounds__(TPB) void retina_kernel(
    const float* __restrict__ x,
    const float* __restrict__ l,
    float* __restrict__ full,
    float* __restrict__ patch)
{
    const int b = blockIdx.x;
    const int tid = threadIdx.x;
    const float4 z4 = make_float4(0.f, 0.f, 0.f, 0.f);

    // Window corner (per-thread; l loads are same-line L1 broadcasts).
    float l0 = fminf(fmaxf(__ldg(&l[2 * b + 0]), -1.0f), 1.0f);
    float l1 = fminf(fmaxf(__ldg(&l[2 * b + 1]), -1.0f), 1.0f);
    const int rs = (int)(0.5f * ((l0 + 1.0f) * 32.0f)) - GG / 2;  // [-8,24]
    const int cs = (int)(0.5f * ((l1 + 1.0f) * 32.0f)) - GG / 2;

    const float* xb = x + (size_t)b * FULL_PER_B;
    float* fb = full + (size_t)b * FULL_PER_B;

    // Per-thread quad geometry: 4 full-phase tasks (4*192 = 768 quads).
    int  w0a[4], offs[4];
    bool ov[4];
    #pragma unroll
    for (int it = 0; it < 4; ++it) {
        int v = it * TPB + tid;             // [0,768) float4 index
        int ch  = v >> 8;
        int rem = v & 255;
        int h   = rem >> 3;
        w0a[it] = (rem & 7) << 2;
        offs[it] = (ch << 10) + (h << 5) + w0a[it];
        ov[it] = (h >= rs) && (h < rs + GG) &&
                 (w0a[it] + 3 >= cs) && (w0a[it] <= cs + GG - 1);
    }

    // ---- Group 1: batched window loads (only real DRAM reads) ----
    float4 xv[4];
    #pragma unroll
    for (int it = 0; it < 4; ++it) {
        xv[it] = z4;
        if (ov[it])
            xv[it] = *(const float4*)(xb + offs[it]);
    }

    // ---- Group 2: independent zero stores (no scoreboard waits) ----
    #pragma unroll
    for (int it = 0; it < 4; ++it) {
        int v = it * TPB + tid;
        if (!ov[it])
            __stcs((float4*)(fb + ((size_t)v << 2)), z4);
    }

    // ---- Group 3: dependent window stores ----
    #pragma unroll
    for (int it = 0; it < 4; ++it) {
        if (ov[it]) {
            int v = it * TPB + tid;
            int w0 = w0a[it];
            float4 out;
            out.x = (w0 + 0 >= cs && w0 + 0 < cs + GG) ? xv[it].x : 0.f;
            out.y = (w0 + 1 >= cs && w0 + 1 < cs + GG) ? xv[it].y : 0.f;
            out.z = (w0 + 2 >= cs && w0 + 2 < cs + GG) ? xv[it].z : 0.f;
            out.w = (w0 + 3 >= cs && w0 + 3 < cs + GG) ? xv[it].w : 0.f;
            __stcs((float4*)(fb + ((size_t)v << 2)), out);
        }
    }

    // ---- Patch phase: exactly 1 float4 task per thread (192 quads) ----
    {
        float* pb = patch + (size_t)b * PATCH_PER_B;
        int e4  = tid;                      // float4 index [0,192)
        int ch  = e4 >> 6;                  // 64 quads per channel
        int rem = e4 & 63;
        int i   = rem >> 2;                 // patch row [0,16)
        int j0  = (rem & 3) << 2;           // first patch col of this float4
        int row = rs + i;
        float4 out = z4;
        if (row >= 0 && row < HH) {
            const float* xr = xb + (ch << 10) + (row << 5);
            int c0 = cs + j0;
            if (c0 + 0 >= 0 && c0 + 0 < HH) out.x = xr[c0 + 0];
            if (c0 + 1 >= 0 && c0 + 1 < HH) out.y = xr[c0 + 1];
            if (c0 + 2 >= 0 && c0 + 2 < HH) out.z = xr[c0 + 2];
            if (c0 + 3 >= 0 && c0 + 3 < HH) out.w = xr[c0 + 3];
        }
        __stcs((float4*)(pb + ((size_t)e4 << 2)), out);
    }
}

extern "C" void kernel_launch(void* const* d_in, const int* in_sizes, int n_in,
                              void* d_out, int out_size)
{
    const float* x = (const float*)d_in[0];   // [16384,3,32,32]
    const float* l = (const float*)d_in[1];   // [16384,2]
    float* full  = (float*)d_out;
    float* patch = (float*)d_out + (size_t)BB * FULL_PER_B;
    retina_kernel<<<BB, TPB>>>(x, l, full, patch);
}

// round 11
// speedup vs baseline: 1.0385x; 1.0385x over previous
#include <cuda_runtime.h>

// Retina glimpse: x [B=16384, C=3, 32, 32] f32, l [B,2] f32 in [-1,1].
// Outputs concatenated into d_out:
//   full  [B,3,32,32] : x masked to the valid part of the 16x16 window, else 0
//   patch [B,3,16,16] : gathered window, 0 where out of [0,32) bounds
//
// FINAL (best-measured, Round-3 configuration; kernel 51.9 us).
// The kernel is HBM-roofline-bound: 283 MB compulsory traffic at the
// ~5.3-5.4 TB/s mixed read/write DRAM ceiling (verified invariant across 10
// structural variants: STG vs TMA bulk, .cs vs default, smem staging,
// dependency splitting, MLP x2, block shapes 192/256, persistent CTAs).

#define BB 16384
#define CC 3
#define HH 32
#define GG 16
#define FULL_PER_B (CC*HH*HH)   // 3072 floats
#define PATCH_PER_B (CC*GG*GG)  // 768 floats

__global__ __launch_bounds__(256) void retina_kernel(
    const float* __restrict__ x,
    const float* __restrict__ l,
    float* __restrict__ full,
    float* __restrict__ patch)
{
    const int b = blockIdx.x;

    // Every thread computes the window corner itself; l loads are same-line
    // L1 broadcasts. No smem, no barrier.
    float l0 = fminf(fmaxf(__ldg(&l[2 * b + 0]), -1.0f), 1.0f);
    float l1 = fminf(fmaxf(__ldg(&l[2 * b + 1]), -1.0f), 1.0f);
    const int rs = (int)(0.5f * ((l0 + 1.0f) * 32.0f)) - GG / 2;
    const int cs = (int)(0.5f * ((l1 + 1.0f) * 32.0f)) - GG / 2;

    const float* xb = x + (size_t)b * FULL_PER_B;
    float* fb = full + (size_t)b * FULL_PER_B;

    // ---------- full phase: 768 float4/sample, 3 per thread ----------
    // Issue all (predicated) loads first, then all stores.
    float4 xv[3];
    int  w0a[3];
    bool ld[3];
    #pragma unroll
    for (int it = 0; it < 3; ++it) {
        int v = it * 256 + threadIdx.x;     // [0,768)
        int ch  = v >> 8;
        int rem = v & 255;
        int h   = rem >> 3;
        int w0  = (rem & 7) << 2;
        w0a[it] = w0;
        bool rowin = (h >= rs) && (h < rs + GG);
        ld[it] = rowin && (w0 + 3 >= cs) && (w0 <= cs + GG - 1);
        xv[it] = make_float4(0.f, 0.f, 0.f, 0.f);
        if (ld[it])
            xv[it] = *(const float4*)(xb + (ch << 10) + (h << 5) + w0);
    }
    #pragma unroll
    for (int it = 0; it < 3; ++it) {
        int v = it * 256 + threadIdx.x;
        int w0 = w0a[it];
        float4 out;
        out.x = (ld[it] && w0 + 0 >= cs && w0 + 0 < cs + GG) ? xv[it].x : 0.f;
        out.y = (ld[it] && w0 + 1 >= cs && w0 + 1 < cs + GG) ? xv[it].y : 0.f;
        out.z = (ld[it] && w0 + 2 >= cs && w0 + 2 < cs + GG) ? xv[it].z : 0.f;
        out.w = (ld[it] && w0 + 3 >= cs && w0 + 3 < cs + GG) ? xv[it].w : 0.f;
        __stcs((float4*)(fb + ((size_t)v << 2)), out);   // streaming: never re-read
    }

    // ---------- patch phase: 192 float4/sample, threads 0..191 ----------
    // Columns j0..j0+3 are contiguous in the patch; gather 4 scalars from x
    // (L1/L2 hits: the full phase just touched these lines).
    if (threadIdx.x < 192) {
        float* pb = patch + (size_t)b * PATCH_PER_B;
        int e4  = threadIdx.x;          // float4 index [0,192)
        int ch  = e4 >> 6;              // 64 float4 per channel (256 floats)
        int rem = e4 & 63;
        int i   = rem >> 2;             // patch row [0,16)
        int j0  = (rem & 3) << 2;       // first patch col of this float4
        int row = rs + i;
        float4 out = make_float4(0.f, 0.f, 0.f, 0.f);
        if (row >= 0 && row < 32) {
            const float* xr = xb + (ch << 10) + (row << 5);
            int c0 = cs + j0;
            if (c0 + 0 >= 0 && c0 + 0 < 32) out.x = xr[c0 + 0];
            if (c0 + 1 >= 0 && c0 + 1 < 32) out.y = xr[c0 + 1];
            if (c0 + 2 >= 0 && c0 + 2 < 32) out.z = xr[c0 + 2];
            if (c0 + 3 >= 0 && c0 + 3 < 32) out.w = xr[c0 + 3];
        }
        __stcs((float4*)(pb + ((size_t)e4 << 2)), out);
    }
}

extern "C" void kernel_launch(void* const* d_in, const int* in_sizes, int n_in,
                              void* d_out, int out_size)
{
    const float* x = (const float*)d_in[0];   // [16384,3,32,32]
    const float* l = (const float*)d_in[1];   // [16384,2]
    float* full  = (float*)d_out;
    float* patch = (float*)d_out + (size_t)BB * FULL_PER_B;
    retina_kernel<<<BB, 256>>>(x, l, full, patch);
}